// round 9
// baseline (speedup 1.0000x reference)
#include <cuda_runtime.h>
#include <cuda_fp16.h>
#include <cstdint>

// NearestEmbed: x (64,64,32,32) f32, emb (64,512) f32
// out f32 = [ quantized 4194304 | argmin 65536 (as float) ]
//
// R9: HMMA coarse + exact fp32 rescue (R6 structure), critical path shortened:
//   - B fragments fetched as LDS.128 (uint4), half the LDS instructions
//   - two independent 2-deep HMMA chains per nt (was one 4-deep chain)
//   - pairwise-min top-2 update (1 update/row/nt instead of 2)

#define THREADS 512            // 16 warps, warp handles 16 rows
#define TILE_M 256             // rows per CTA tile
#define GRID 128
#define TILES_PER_CTA 2        // 256 tiles total / 128 CTAs
#define EMB_D 64
#define EMB_K 512
#define HW 1024
#define MARGIN 0.04f

// smem layout (bytes)
#define SM_FRAGS 0                       // u32 frags[64 nt][2 kp][32 lane][4] = 64KB
#define SM_EMB   65536                   // f32 emb_s[64][512] = 128KB
#define SM_NORMS (SM_EMB + 131072)       // f32 [512] = 2KB
#define SM_WIN   (SM_NORMS + 2048)       // i32 [256]
#define SM_QUEUE (SM_WIN + 1024)         // i32 [256]
#define SM_QCNT  (SM_QUEUE + 1024)       // i32
#define SM_XS    (SM_QCNT + 16)          // f32 [16 warps][64] = 4KB
#define SM_TOTAL (SM_XS + 4096)

__device__ __forceinline__ uint32_t packh2(float a, float b) {
    __half2 h = __floats2half2_rn(a, b);
    return *reinterpret_cast<uint32_t*>(&h);
}

__device__ __forceinline__ void hmma16816(float& c0, float& c1, float& c2, float& c3,
                                          uint32_t a0, uint32_t a1, uint32_t a2, uint32_t a3,
                                          uint32_t b0, uint32_t b1) {
    asm volatile("mma.sync.aligned.m16n8k16.row.col.f32.f16.f16.f32 "
                 "{%0,%1,%2,%3}, {%4,%5,%6,%7}, {%8,%9}, {%0,%1,%2,%3};"
                 : "+f"(c0), "+f"(c1), "+f"(c2), "+f"(c3)
                 : "r"(a0), "r"(a1), "r"(a2), "r"(a3), "r"(b0), "r"(b1));
}

__global__ __launch_bounds__(THREADS, 1)
void vq_hmma_kernel(const float* __restrict__ x,
                    const float* __restrict__ emb,
                    float* __restrict__ out_q,
                    float* __restrict__ out_idx)
{
    extern __shared__ char smem[];
    uint32_t* frags   = reinterpret_cast<uint32_t*>(smem + SM_FRAGS);
    float*    emb_s   = reinterpret_cast<float*>(smem + SM_EMB);
    float*    norms   = reinterpret_cast<float*>(smem + SM_NORMS);
    int*      winners = reinterpret_cast<int*>(smem + SM_WIN);
    int*      queue   = reinterpret_cast<int*>(smem + SM_QUEUE);
    int*      qcnt    = reinterpret_cast<int*>(smem + SM_QCNT);
    float*    xscr    = reinterpret_cast<float*>(smem + SM_XS);

    const int tid  = threadIdx.x;
    const int warp = tid >> 5;
    const int lane = tid & 31;
    const int gidq = lane & 3;
    const int grp  = lane >> 2;

    // ---- Prologue (once per CTA) ----
    for (int i = tid; i < EMB_D * EMB_K; i += THREADS) emb_s[i] = emb[i];
    if (tid == 0) *qcnt = 0;
    __syncthreads();

    for (int k = tid; k < EMB_K; k += THREADS) {
        float s = 0.f;
        #pragma unroll
        for (int d = 0; d < EMB_D; d++) {
            float v = emb_s[d * EMB_K + k];
            s = fmaf(v, v, s);
        }
        norms[k] = s;
    }
    // B fragments (uint4 layout): frags[(((nt*2 + kp)*32) + lane)*4 + w]
    //   ks = kp*2 + (w>>1), j = w&1, n = nt*8 + lane/4, d0 = ks*16 + 2*(lane%4) + 8*j
    for (int f = tid; f < 64 * 2 * 32 * 4; f += THREADS) {
        int w  = f & 3;
        int ln = (f >> 2) & 31;
        int kp = (f >> 7) & 1;
        int nt = f >> 8;
        int ks = kp * 2 + (w >> 1);
        int j  = w & 1;
        int n  = nt * 8 + (ln >> 2);
        int d0 = ks * 16 + 2 * (ln & 3) + 8 * j;
        frags[f] = packh2(emb_s[d0 * EMB_K + n], emb_s[(d0 + 1) * EMB_K + n]);
    }
    __syncthreads();

    for (int it = 0; it < TILES_PER_CTA; it++) {
        const int tile = blockIdx.x * TILES_PER_CTA + it;
        const int row_base = tile * TILE_M;
        const int b = row_base >> 10;
        const int hw_base = row_base & (HW - 1);
        const float* xb = x + (size_t)b * (EMB_D * HW) + hw_base;   // x(row,d)=xb[d*HW+row]

        // ---- A fragments: this warp's 16 rows ----
        const float* xw = xb + warp * 16;
        uint32_t A[4][4];
        {
            const int q2 = gidq * 2;
            #pragma unroll
            for (int ks = 0; ks < 4; ks++) {
                int d = ks * 16 + q2;
                A[ks][0] = packh2(xw[d * HW + grp],           xw[(d + 1) * HW + grp]);
                A[ks][1] = packh2(xw[d * HW + grp + 8],       xw[(d + 1) * HW + grp + 8]);
                A[ks][2] = packh2(xw[(d + 8) * HW + grp],     xw[(d + 9) * HW + grp]);
                A[ks][3] = packh2(xw[(d + 8) * HW + grp + 8], xw[(d + 9) * HW + grp + 8]);
            }
        }

        // ---- coarse scan over 64 n-tiles ----
        float b1a = __int_as_float(0x7f800000), b2a = b1a; int k1a = 0;  // row grp
        float b1b = b1a, b2b = b1a; int k1b = 0;                          // row grp+8

        const uint4* fr4 = reinterpret_cast<const uint4*>(frags);
        #pragma unroll 4
        for (int nt = 0; nt < 64; nt++) {
            // two independent HMMA chains (ks 0-1 and ks 2-3)
            float c0 = 0.f, c1 = 0.f, c2 = 0.f, c3 = 0.f;
            float e0 = 0.f, e1 = 0.f, e2 = 0.f, e3 = 0.f;
            uint4 qa = fr4[(nt * 2 + 0) * 32 + lane];   // LDS.128: ks0 (x,y), ks1 (z,w)
            uint4 qb = fr4[(nt * 2 + 1) * 32 + lane];   // LDS.128: ks2 (x,y), ks3 (z,w)
            hmma16816(c0, c1, c2, c3, A[0][0], A[0][1], A[0][2], A[0][3], qa.x, qa.y);
            hmma16816(e0, e1, e2, e3, A[2][0], A[2][1], A[2][2], A[2][3], qb.x, qb.y);
            hmma16816(c0, c1, c2, c3, A[1][0], A[1][1], A[1][2], A[1][3], qa.z, qa.w);
            hmma16816(e0, e1, e2, e3, A[3][0], A[3][1], A[3][2], A[3][3], qb.z, qb.w);

            const int n0 = nt * 8 + gidq * 2;
            float2 nr = *reinterpret_cast<const float2*>(norms + n0);
            float s0 = fmaf(-2.f, c0 + e0, nr.x);
            float s1 = fmaf(-2.f, c1 + e1, nr.y);
            float s2 = fmaf(-2.f, c2 + e2, nr.x);
            float s3 = fmaf(-2.f, c3 + e3, nr.y);

            // pairwise-min top-2 update, row a (codes n0, n0+1)
            {
                float sm = fminf(s0, s1);
                float pm = fmaxf(s0, s1);
                int   km = n0 + (s1 < s0 ? 1 : 0);
                if (sm < b1a) { b2a = fminf(b1a, pm); b1a = sm; k1a = km; }
                else          { b2a = fminf(b2a, sm); }
            }
            // row b (grp+8)
            {
                float sm = fminf(s2, s3);
                float pm = fmaxf(s2, s3);
                int   km = n0 + (s3 < s2 ? 1 : 0);
                if (sm < b1b) { b2b = fminf(b1b, pm); b1b = sm; k1b = km; }
                else          { b2b = fminf(b2b, sm); }
            }
        }

        // ---- merge across the 4 lanes of each row-group ----
        #pragma unroll
        for (int off = 1; off <= 2; off <<= 1) {
            float ob1 = __shfl_xor_sync(0xffffffffu, b1a, off);
            int   ok1 = __shfl_xor_sync(0xffffffffu, k1a, off);
            float ob2 = __shfl_xor_sync(0xffffffffu, b2a, off);
            float nb2 = fminf(fmaxf(b1a, ob1), fminf(b2a, ob2));
            bool take = (ob1 < b1a) || (ob1 == b1a && ok1 < k1a);
            b1a = take ? ob1 : b1a; k1a = take ? ok1 : k1a; b2a = nb2;

            float pb1 = __shfl_xor_sync(0xffffffffu, b1b, off);
            int   pk1 = __shfl_xor_sync(0xffffffffu, k1b, off);
            float pb2 = __shfl_xor_sync(0xffffffffu, b2b, off);
            float qb2 = fminf(fmaxf(b1b, pb1), fminf(b2b, pb2));
            bool tk2 = (pb1 < b1b) || (pb1 == b1b && pk1 < k1b);
            b1b = tk2 ? pb1 : b1b; k1b = tk2 ? pk1 : k1b; b2b = qb2;
        }

        if (gidq == 0) {
            int lr = warp * 16 + grp;
            if (b2a - b1a <= MARGIN) { int qi = atomicAdd(qcnt, 1); queue[qi] = lr; }
            else winners[lr] = k1a;
            int lr2 = lr + 8;
            if (b2b - b1b <= MARGIN) { int qi = atomicAdd(qcnt, 1); queue[qi] = lr2; }
            else winners[lr2] = k1b;
        }
        __syncthreads();

        // ---- exact fp32 rescan for ambiguous rows (rare) ----
        const int nq = *qcnt;
        for (int i = warp; i < nq; i += 16) {
            int lr = queue[i];
            const float* xg = xb + lr;
            float* xs = xscr + warp * 64;
            xs[lane] = xg[(size_t)lane * HW];
            xs[lane + 32] = xg[(size_t)(lane + 32) * HW];
            __syncwarp();
            float best = __int_as_float(0x7f800000);
            int bk = 0;
            #pragma unroll
            for (int j = 0; j < 16; j++) {
                int k = lane + 32 * j;
                float acc = 0.f;
                #pragma unroll
                for (int d = 0; d < EMB_D; d++)
                    acc = fmaf(xs[d], emb_s[d * EMB_K + k], acc);
                float sc = fmaf(-2.f, acc, norms[k]);
                if (sc < best) { best = sc; bk = k; }
            }
            #pragma unroll
            for (int off = 16; off >= 1; off >>= 1) {
                float os = __shfl_xor_sync(0xffffffffu, best, off);
                int   ok = __shfl_xor_sync(0xffffffffu, bk, off);
                bool take = (os < best) || (os == best && ok < bk);
                best = take ? os : best;
                bk = take ? ok : bk;
            }
            if (lane == 0) winners[lr] = bk;
            __syncwarp();
        }
        __syncthreads();

        // ---- outputs ----
        float* oq = out_q + (size_t)b * (EMB_D * HW) + hw_base;
        for (int i = tid; i < TILE_M * EMB_D; i += THREADS) {
            int r = i & (TILE_M - 1);
            int d = i >> 8;
            oq[(size_t)d * HW + r] = emb_s[d * EMB_K + winners[r]];
        }
        if (tid < TILE_M) out_idx[row_base + tid] = (float)winners[tid];
        if (tid == 0) *qcnt = 0;
        __syncthreads();
    }
}

extern "C" void kernel_launch(void* const* d_in, const int* in_sizes, int n_in,
                              void* d_out, int out_size)
{
    const float* x   = (const float*)d_in[0];   // 4194304 f32
    const float* emb = (const float*)d_in[1];   // 32768 f32
    float* out_q = (float*)d_out;
    float* out_i = (float*)d_out + (size_t)4194304;

    cudaFuncSetAttribute(vq_hmma_kernel,
                         cudaFuncAttributeMaxDynamicSharedMemorySize, SM_TOTAL);
    vq_hmma_kernel<<<GRID, THREADS, SM_TOTAL>>>(x, emb, out_q, out_i);
}

// round 10
// speedup vs baseline: 1.0407x; 1.0407x over previous
#include <cuda_runtime.h>
#include <cuda_fp16.h>
#include <cstdint>

// NearestEmbed: x (64,64,32,32) f32, emb (64,512) f32
// out f32 = [ quantized 4194304 | argmin 65536 (as float) ]
//
// R10: R6 coarse loop (best measured), restructured so that after the one
// prologue barrier every warp is fully autonomous for its 16 rows:
// A-load -> coarse -> merge -> in-warp rescue -> in-warp output, no CTA
// barriers between phases or tiles. Warps free-run and overlap latencies.

#define THREADS 512            // 16 warps, warp owns 16 rows per tile
#define TILE_M 256
#define GRID 128
#define TILES_PER_CTA 2
#define EMB_D 64
#define EMB_K 512
#define HW 1024
#define MARGIN 0.04f

// smem layout (bytes)
#define SM_FRAGS 0                       // u32 frags[64 nt][4 ks][32 lane][2] = 64KB
#define SM_EMB   65536                   // f32 emb_s[64][512] = 128KB
#define SM_NORMS (SM_EMB + 131072)       // f32 [512] = 2KB
#define SM_WSM   (SM_NORMS + 2048)       // i32 [16 warps][16 rows] = 1KB
#define SM_XS    (SM_WSM + 1024)         // f32 [16 warps][64] = 4KB
#define SM_TOTAL (SM_XS + 4096)

__device__ __forceinline__ uint32_t packh2(float a, float b) {
    __half2 h = __floats2half2_rn(a, b);
    return *reinterpret_cast<uint32_t*>(&h);
}

__device__ __forceinline__ void hmma16816(float& c0, float& c1, float& c2, float& c3,
                                          uint32_t a0, uint32_t a1, uint32_t a2, uint32_t a3,
                                          uint32_t b0, uint32_t b1) {
    asm volatile("mma.sync.aligned.m16n8k16.row.col.f32.f16.f16.f32 "
                 "{%0,%1,%2,%3}, {%4,%5,%6,%7}, {%8,%9}, {%0,%1,%2,%3};"
                 : "+f"(c0), "+f"(c1), "+f"(c2), "+f"(c3)
                 : "r"(a0), "r"(a1), "r"(a2), "r"(a3), "r"(b0), "r"(b1));
}

__global__ __launch_bounds__(THREADS, 1)
void vq_hmma_kernel(const float* __restrict__ x,
                    const float* __restrict__ emb,
                    float* __restrict__ out_q,
                    float* __restrict__ out_idx)
{
    extern __shared__ char smem[];
    uint32_t* frags = reinterpret_cast<uint32_t*>(smem + SM_FRAGS);
    float*    emb_s = reinterpret_cast<float*>(smem + SM_EMB);
    float*    norms = reinterpret_cast<float*>(smem + SM_NORMS);

    const int tid  = threadIdx.x;
    const int warp = tid >> 5;
    const int lane = tid & 31;
    const int gidq = lane & 3;
    const int grp  = lane >> 2;

    int*   wsm  = reinterpret_cast<int*>(smem + SM_WSM) + warp * 16;   // this warp's winners
    float* xs   = reinterpret_cast<float*>(smem + SM_XS) + warp * 64;  // this warp's rescue row

    // ---- Prologue (once per CTA; the only CTA barrier) ----
    for (int i = tid; i < EMB_D * EMB_K; i += THREADS) emb_s[i] = emb[i];
    __syncthreads();

    for (int k = tid; k < EMB_K; k += THREADS) {
        float s = 0.f;
        #pragma unroll
        for (int d = 0; d < EMB_D; d++) {
            float v = emb_s[d * EMB_K + k];
            s = fmaf(v, v, s);
        }
        norms[k] = s;
    }
    // B fragments: frags[((nt*4+ks)*32 + lane)*2 + j]
    for (int f = tid; f < 64 * 4 * 32 * 2; f += THREADS) {
        int j  = f & 1;
        int ln = (f >> 1) & 31;
        int ks = (f >> 6) & 3;
        int nt = f >> 8;
        int n  = nt * 8 + (ln >> 2);
        int d0 = ks * 16 + 2 * (ln & 3) + 8 * j;
        frags[f] = packh2(emb_s[d0 * EMB_K + n], emb_s[(d0 + 1) * EMB_K + n]);
    }
    __syncthreads();   // after this, warps are fully independent

    for (int it = 0; it < TILES_PER_CTA; it++) {
        const int tile = blockIdx.x * TILES_PER_CTA + it;
        const int row_base = tile * TILE_M;
        const int b = row_base >> 10;
        const int hw_base = row_base & (HW - 1);
        const float* xb = x + (size_t)b * (EMB_D * HW) + hw_base;   // x(row,d)=xb[d*HW+row]
        const int wrow = warp * 16;                                  // warp's first row in tile

        // ---- A fragments: this warp's 16 rows ----
        const float* xw = xb + wrow;
        uint32_t A[4][4];
        {
            const int q2 = gidq * 2;
            #pragma unroll
            for (int ks = 0; ks < 4; ks++) {
                int d = ks * 16 + q2;
                A[ks][0] = packh2(xw[d * HW + grp],           xw[(d + 1) * HW + grp]);
                A[ks][1] = packh2(xw[d * HW + grp + 8],       xw[(d + 1) * HW + grp + 8]);
                A[ks][2] = packh2(xw[(d + 8) * HW + grp],     xw[(d + 9) * HW + grp]);
                A[ks][3] = packh2(xw[(d + 8) * HW + grp + 8], xw[(d + 9) * HW + grp + 8]);
            }
        }

        // ---- coarse scan over 64 n-tiles (identical to R6) ----
        float b1a = __int_as_float(0x7f800000), b2a = b1a; int k1a = 0;  // row grp
        float b1b = b1a, b2b = b1a; int k1b = 0;                          // row grp+8

        const uint2* fr2 = reinterpret_cast<const uint2*>(frags);
        #pragma unroll 4
        for (int nt = 0; nt < 64; nt++) {
            float c0 = 0.f, c1 = 0.f, c2 = 0.f, c3 = 0.f;
            #pragma unroll
            for (int ks = 0; ks < 4; ks++) {
                uint2 bb = fr2[(nt * 4 + ks) * 32 + lane];
                hmma16816(c0, c1, c2, c3, A[ks][0], A[ks][1], A[ks][2], A[ks][3], bb.x, bb.y);
            }
            const int n0 = nt * 8 + gidq * 2;
            float2 nr = *reinterpret_cast<const float2*>(norms + n0);
            float s0 = fmaf(-2.f, c0, nr.x);
            float s1 = fmaf(-2.f, c1, nr.y);
            float s2 = fmaf(-2.f, c2, nr.x);
            float s3 = fmaf(-2.f, c3, nr.y);
            if (s0 < b1a) { b2a = b1a; b1a = s0; k1a = n0; } else b2a = fminf(b2a, s0);
            if (s1 < b1a) { b2a = b1a; b1a = s1; k1a = n0 + 1; } else b2a = fminf(b2a, s1);
            if (s2 < b1b) { b2b = b1b; b1b = s2; k1b = n0; } else b2b = fminf(b2b, s2);
            if (s3 < b1b) { b2b = b1b; b1b = s3; k1b = n0 + 1; } else b2b = fminf(b2b, s3);
        }

        // ---- merge across the 4 lanes of each row-group ----
        #pragma unroll
        for (int off = 1; off <= 2; off <<= 1) {
            float ob1 = __shfl_xor_sync(0xffffffffu, b1a, off);
            int   ok1 = __shfl_xor_sync(0xffffffffu, k1a, off);
            float ob2 = __shfl_xor_sync(0xffffffffu, b2a, off);
            float nb2 = fminf(fmaxf(b1a, ob1), fminf(b2a, ob2));
            bool take = (ob1 < b1a) || (ob1 == b1a && ok1 < k1a);
            b1a = take ? ob1 : b1a; k1a = take ? ok1 : k1a; b2a = nb2;

            float pb1 = __shfl_xor_sync(0xffffffffu, b1b, off);
            int   pk1 = __shfl_xor_sync(0xffffffffu, k1b, off);
            float pb2 = __shfl_xor_sync(0xffffffffu, b2b, off);
            float qb2 = fminf(fmaxf(b1b, pb1), fminf(b2b, pb2));
            bool tk2 = (pb1 < b1b) || (pb1 == b1b && pk1 < k1b);
            b1b = tk2 ? pb1 : b1b; k1b = tk2 ? pk1 : k1b; b2b = qb2;
        }

        // ---- in-warp: record winners, mark ambiguous rows ----
        // lane 4*grp holds results for rows grp (a) and grp+8 (b)
        bool ownA = (gidq == 0);
        bool ambA = ownA && (b2a - b1a <= MARGIN);
        bool ambB = ownA && (b2b - b1b <= MARGIN);
        if (ownA) {
            wsm[grp]     = k1a;
            wsm[grp + 8] = k1b;
        }
        uint32_t mA = __ballot_sync(0xffffffffu, ambA);   // bits at 4*grp -> rows 0..7
        uint32_t mB = __ballot_sync(0xffffffffu, ambB);   // bits at 4*grp -> rows 8..15
        __syncwarp();

        // combined 16-bit ambiguous-row mask
        uint32_t amb = 0;
        #pragma unroll
        for (int g = 0; g < 8; g++) {
            amb |= ((mA >> (4 * g)) & 1u) << g;
            amb |= ((mB >> (4 * g)) & 1u) << (g + 8);
        }

        // ---- in-warp exact fp32 rescue for ambiguous rows (rare) ----
        while (amb) {
            int r = __ffs(amb) - 1;
            amb &= amb - 1;
            const float* xg = xb + wrow + r;
            xs[lane]      = xg[(size_t)lane * HW];
            xs[lane + 32] = xg[(size_t)(lane + 32) * HW];
            __syncwarp();
            float best = __int_as_float(0x7f800000);
            int bk = 0;
            #pragma unroll
            for (int j = 0; j < 16; j++) {
                int k = lane + 32 * j;
                float acc = 0.f;
                #pragma unroll
                for (int d = 0; d < EMB_D; d++)
                    acc = fmaf(xs[d], emb_s[d * EMB_K + k], acc);
                float sc = fmaf(-2.f, acc, norms[k]);
                if (sc < best) { best = sc; bk = k; }
            }
            #pragma unroll
            for (int off = 16; off >= 1; off >>= 1) {
                float os = __shfl_xor_sync(0xffffffffu, best, off);
                int   ok = __shfl_xor_sync(0xffffffffu, bk, off);
                bool take = (os < best) || (os == best && ok < bk);
                best = take ? os : best;
                bk = take ? ok : bk;
            }
            if (lane == 0) wsm[r] = bk;
            __syncwarp();
        }
        __syncwarp();

        // ---- in-warp outputs: this warp's 16 rows ----
        float* oq = out_q + (size_t)b * (EMB_D * HW) + hw_base + wrow;
        #pragma unroll
        for (int i = lane; i < 16 * EMB_D; i += 32) {
            int r = i & 15;
            int d = i >> 4;
            oq[(size_t)d * HW + r] = emb_s[d * EMB_K + wsm[r]];
        }
        if (lane < 16) out_idx[row_base + wrow + lane] = (float)wsm[lane];
        __syncwarp();
    }
}

extern "C" void kernel_launch(void* const* d_in, const int* in_sizes, int n_in,
                              void* d_out, int out_size)
{
    const float* x   = (const float*)d_in[0];   // 4194304 f32
    const float* emb = (const float*)d_in[1];   // 32768 f32
    float* out_q = (float*)d_out;
    float* out_i = (float*)d_out + (size_t)4194304;

    cudaFuncSetAttribute(vq_hmma_kernel,
                         cudaFuncAttributeMaxDynamicSharedMemorySize, SM_TOTAL);
    vq_hmma_kernel<<<GRID, THREADS, SM_TOTAL>>>(x, emb, out_q, out_i);
}